// round 2
// baseline (speedup 1.0000x reference)
#include <cuda_runtime.h>

// ---------------- problem constants ----------------
#define BATCH 4
#define SEQ   2048
#define CDIM  1024
#define NH    16
#define HD    64
#define MROWS (BATCH*SEQ)     // 8192
#define QKVN  (3*CDIM)        // 3072
// softmax scale folded with log2(e) so we can use ex2.approx
#define SM_SCALE (0.125f * 1.4426950408889634f)

// ---------------- scratch (static device arrays; no allocation) ----------------
__device__ __align__(16) float g_q[(size_t)BATCH*NH*SEQ*HD];   // 32 MB
__device__ __align__(16) float g_k[(size_t)BATCH*NH*SEQ*HD];   // 32 MB
__device__ __align__(16) float g_v[(size_t)BATCH*NH*SEQ*HD];   // 32 MB
__device__ __align__(16) float g_att[(size_t)MROWS*CDIM];      // 32 MB

__device__ __forceinline__ float ex2f(float x) {
    float y;
    asm("ex2.approx.ftz.f32 %0, %1;" : "=f"(y) : "f"(x));
    return y;
}

// =====================================================================
// Kernel 1: QKV GEMM  (8192 x 3072 x 1024), epilogue scatters to q/k/v
// 128x128 block tile, 16 k-slice, 256 threads, 8x8 per-thread microtile
// =====================================================================
__global__ __launch_bounds__(256)
void qkv_gemm(const float* __restrict__ x, const float* __restrict__ w,
              const float* __restrict__ bias) {
    __shared__ float As[16][128];
    __shared__ float Bs[16][128];

    const int tid = threadIdx.x;
    const int tx = tid & 15;          // 0..15  -> 8 cols each
    const int ty = tid >> 4;          // 0..15  -> 8 rows each
    const int bm0 = blockIdx.y * 128;
    const int bn0 = blockIdx.x * 128;

    float acc[8][8];
#pragma unroll
    for (int i = 0; i < 8; ++i)
#pragma unroll
        for (int j = 0; j < 8; ++j) acc[i][j] = 0.f;

    for (int kt = 0; kt < CDIM; kt += 16) {
        // load A tile (128 rows x 16 k), transpose into As[k][m]
#pragma unroll
        for (int it = 0; it < 2; ++it) {
            int idx = tid + it * 256;           // 0..511
            int r  = idx >> 2;                  // row in tile
            int kq = (idx & 3) << 2;            // k offset (0,4,8,12)
            float4 v = *(const float4*)(x + (size_t)(bm0 + r) * CDIM + kt + kq);
            As[kq + 0][r] = v.x; As[kq + 1][r] = v.y;
            As[kq + 2][r] = v.z; As[kq + 3][r] = v.w;
        }
        // load B tile (16 k x 128 cols), direct
#pragma unroll
        for (int it = 0; it < 2; ++it) {
            int idx = tid + it * 256;
            int kr = idx >> 5;                  // 0..15
            int c  = (idx & 31) << 2;           // 0..124
            *(float4*)&Bs[kr][c] =
                *(const float4*)(w + (size_t)(kt + kr) * QKVN + bn0 + c);
        }
        __syncthreads();

#pragma unroll
        for (int kk = 0; kk < 16; ++kk) {
            float a[8], b[8];
            *(float4*)(a)     = *(float4*)&As[kk][ty * 8];
            *(float4*)(a + 4) = *(float4*)&As[kk][ty * 8 + 4];
            *(float4*)(b)     = *(float4*)&Bs[kk][tx * 8];
            *(float4*)(b + 4) = *(float4*)&Bs[kk][tx * 8 + 4];
#pragma unroll
            for (int i = 0; i < 8; ++i)
#pragma unroll
                for (int j = 0; j < 8; ++j) acc[i][j] += a[i] * b[j];
        }
        __syncthreads();
    }

    // epilogue: add bias, scatter into q (pre-scaled), k, v  [B,H,N,D]
#pragma unroll
    for (int i = 0; i < 8; ++i) {
        int row = bm0 + ty * 8 + i;
        int bb = row >> 11;
        int n  = row & 2047;
#pragma unroll
        for (int jj = 0; jj < 8; jj += 4) {
            int col = bn0 + tx * 8 + jj;
            int t   = col >> 10;
            int rem = col & 1023;
            int h   = rem >> 6;
            int d   = rem & 63;
            float4 o;
            o.x = acc[i][jj + 0] + __ldg(bias + col + 0);
            o.y = acc[i][jj + 1] + __ldg(bias + col + 1);
            o.z = acc[i][jj + 2] + __ldg(bias + col + 2);
            o.w = acc[i][jj + 3] + __ldg(bias + col + 3);
            size_t dst = ((size_t)((bb * NH + h) * SEQ + n)) * HD + d;
            if (t == 0) {
                o.x *= SM_SCALE; o.y *= SM_SCALE; o.z *= SM_SCALE; o.w *= SM_SCALE;
                *(float4*)&g_q[dst] = o;
            } else if (t == 1) {
                *(float4*)&g_k[dst] = o;
            } else {
                *(float4*)&g_v[dst] = o;
            }
        }
    }
}

// =====================================================================
// Kernel 2: flash attention, one query row per thread.
// block = 128 threads = 128 q rows; grid = (SEQ/128, B*H)
// K/V tiles of 64 keys staged in smem; online softmax in chunks of 16.
// q is pre-scaled by SCALE*log2(e) -> softmax uses ex2 directly.
// =====================================================================
__global__ __launch_bounds__(128)
void attn_kernel() {
    __shared__ float Ks[64][64];
    __shared__ float Vs[64][64];

    const int tid = threadIdx.x;
    const int bh  = blockIdx.y;
    const int row = blockIdx.x * 128 + tid;

    const float* qp = g_q + ((size_t)bh * SEQ + row) * HD;
    float q[64], o[64];
#pragma unroll
    for (int d4 = 0; d4 < 64; d4 += 4) {
        float4 v = *(const float4*)(qp + d4);
        q[d4] = v.x; q[d4 + 1] = v.y; q[d4 + 2] = v.z; q[d4 + 3] = v.w;
    }
#pragma unroll
    for (int d = 0; d < 64; ++d) o[d] = 0.f;

    float m = -1e30f, l = 0.f;
    const float4* kbase = (const float4*)(g_k + (size_t)bh * SEQ * HD);
    const float4* vbase = (const float4*)(g_v + (size_t)bh * SEQ * HD);
    float4* Ks4 = (float4*)Ks;
    float4* Vs4 = (float4*)Vs;

#pragma unroll 1
    for (int kt = 0; kt < SEQ / 64; ++kt) {
        const float4* ks = kbase + (size_t)kt * 64 * 16;   // 64 rows * 16 float4
        const float4* vs = vbase + (size_t)kt * 64 * 16;
#pragma unroll
        for (int it = 0; it < 8; ++it) {
            Ks4[tid + it * 128] = ks[tid + it * 128];
            Vs4[tid + it * 128] = vs[tid + it * 128];
        }
        __syncthreads();

#pragma unroll 1
        for (int ch = 0; ch < 64; ch += 16) {
            float s[16];
#pragma unroll
            for (int j = 0; j < 16; ++j) {
                const float* kr = &Ks[ch + j][0];
                float a0 = 0.f, a1 = 0.f;
#pragma unroll
                for (int d4 = 0; d4 < 64; d4 += 8) {
                    float4 k0 = *(const float4*)(kr + d4);
                    float4 k1 = *(const float4*)(kr + d4 + 4);
                    a0 += q[d4 + 0] * k0.x; a0 += q[d4 + 1] * k0.y;
                    a0 += q[d4 + 2] * k0.z; a0 += q[d4 + 3] * k0.w;
                    a1 += q[d4 + 4] * k1.x; a1 += q[d4 + 5] * k1.y;
                    a1 += q[d4 + 6] * k1.z; a1 += q[d4 + 7] * k1.w;
                }
                s[j] = a0 + a1;
            }
            float cmax = s[0];
#pragma unroll
            for (int j = 1; j < 16; ++j) cmax = fmaxf(cmax, s[j]);
            float mnew = fmaxf(m, cmax);
            float scale = ex2f(m - mnew);
            float psum = 0.f;
#pragma unroll
            for (int j = 0; j < 16; ++j) {
                s[j] = ex2f(s[j] - mnew);
                psum += s[j];
            }
            l = l * scale + psum;
#pragma unroll
            for (int d = 0; d < 64; ++d) o[d] *= scale;
#pragma unroll
            for (int j = 0; j < 16; ++j) {
                const float* vr = &Vs[ch + j][0];
                float p = s[j];
#pragma unroll
                for (int d4 = 0; d4 < 64; d4 += 4) {
                    float4 v4 = *(const float4*)(vr + d4);
                    o[d4 + 0] += p * v4.x; o[d4 + 1] += p * v4.y;
                    o[d4 + 2] += p * v4.z; o[d4 + 3] += p * v4.w;
                }
            }
            m = mnew;
        }
        __syncthreads();
    }

    float inv = 1.f / l;
    int b = bh >> 4, h = bh & 15;
    float* op = g_att + ((size_t)(b * SEQ + row)) * CDIM + h * HD;
#pragma unroll
    for (int d4 = 0; d4 < 64; d4 += 4) {
        float4 ov;
        ov.x = o[d4 + 0] * inv; ov.y = o[d4 + 1] * inv;
        ov.z = o[d4 + 2] * inv; ov.w = o[d4 + 3] * inv;
        *(float4*)(op + d4) = ov;
    }
}

// =====================================================================
// Kernel 3: output projection GEMM (8192 x 1024 x 1024) + bias -> d_out
// =====================================================================
__global__ __launch_bounds__(256)
void proj_gemm(const float* __restrict__ w, const float* __restrict__ bias,
               float* __restrict__ out) {
    __shared__ float As[16][128];
    __shared__ float Bs[16][128];

    const int tid = threadIdx.x;
    const int tx = tid & 15;
    const int ty = tid >> 4;
    const int bm0 = blockIdx.y * 128;
    const int bn0 = blockIdx.x * 128;

    float acc[8][8];
#pragma unroll
    for (int i = 0; i < 8; ++i)
#pragma unroll
        for (int j = 0; j < 8; ++j) acc[i][j] = 0.f;

    for (int kt = 0; kt < CDIM; kt += 16) {
#pragma unroll
        for (int it = 0; it < 2; ++it) {
            int idx = tid + it * 256;
            int r  = idx >> 2;
            int kq = (idx & 3) << 2;
            float4 v = *(const float4*)(g_att + (size_t)(bm0 + r) * CDIM + kt + kq);
            As[kq + 0][r] = v.x; As[kq + 1][r] = v.y;
            As[kq + 2][r] = v.z; As[kq + 3][r] = v.w;
        }
#pragma unroll
        for (int it = 0; it < 2; ++it) {
            int idx = tid + it * 256;
            int kr = idx >> 5;
            int c  = (idx & 31) << 2;
            *(float4*)&Bs[kr][c] =
                *(const float4*)(w + (size_t)(kt + kr) * CDIM + bn0 + c);
        }
        __syncthreads();

#pragma unroll
        for (int kk = 0; kk < 16; ++kk) {
            float a[8], b[8];
            *(float4*)(a)     = *(float4*)&As[kk][ty * 8];
            *(float4*)(a + 4) = *(float4*)&As[kk][ty * 8 + 4];
            *(float4*)(b)     = *(float4*)&Bs[kk][tx * 8];
            *(float4*)(b + 4) = *(float4*)&Bs[kk][tx * 8 + 4];
#pragma unroll
            for (int i = 0; i < 8; ++i)
#pragma unroll
                for (int j = 0; j < 8; ++j) acc[i][j] += a[i] * b[j];
        }
        __syncthreads();
    }

#pragma unroll
    for (int i = 0; i < 8; ++i) {
        int row = bm0 + ty * 8 + i;
#pragma unroll
        for (int jj = 0; jj < 8; jj += 4) {
            int col = bn0 + tx * 8 + jj;
            float4 o;
            o.x = acc[i][jj + 0] + __ldg(bias + col + 0);
            o.y = acc[i][jj + 1] + __ldg(bias + col + 1);
            o.z = acc[i][jj + 2] + __ldg(bias + col + 2);
            o.w = acc[i][jj + 3] + __ldg(bias + col + 3);
            *(float4*)(out + (size_t)row * CDIM + col) = o;
        }
    }
}

// =====================================================================
extern "C" void kernel_launch(void* const* d_in, const int* in_sizes, int n_in,
                              void* d_out, int out_size) {
    const float* x      = (const float*)d_in[0];
    const float* w_qkv  = (const float*)d_in[1];
    const float* b_qkv  = (const float*)d_in[2];
    const float* w_proj = (const float*)d_in[3];
    const float* b_proj = (const float*)d_in[4];
    float* out = (float*)d_out;

    qkv_gemm<<<dim3(QKVN / 128, MROWS / 128), 256>>>(x, w_qkv, b_qkv);
    attn_kernel<<<dim3(SEQ / 128, BATCH * NH), 128>>>();
    proj_gemm<<<dim3(CDIM / 128, MROWS / 128), 256>>>(w_proj, b_proj, out);
}

// round 3
// speedup vs baseline: 1.0051x; 1.0051x over previous
#include <cuda_runtime.h>

// ---------------- problem constants ----------------
#define BATCH 4
#define SEQ   2048
#define CDIM  1024
#define NH    16
#define HD    64
#define MROWS (BATCH*SEQ)     // 8192
#define QKVN  (3*CDIM)        // 3072
// softmax scale folded with log2(e) so we can use ex2.approx
#define SM_SCALE (0.125f * 1.4426950408889634f)

// ---------------- scratch (static device arrays; no allocation) ----------------
__device__ __align__(16) float g_q[(size_t)BATCH*NH*SEQ*HD];   // 32 MB
__device__ __align__(16) float g_k[(size_t)BATCH*NH*SEQ*HD];   // 32 MB
__device__ __align__(16) float g_v[(size_t)BATCH*NH*SEQ*HD];   // 32 MB
__device__ __align__(16) float g_att[(size_t)MROWS*CDIM];      // 32 MB

__device__ __forceinline__ float ex2f(float x) {
    float y;
    asm("ex2.approx.ftz.f32 %0, %1;" : "=f"(y) : "f"(x));
    return y;
}

// =====================================================================
// Kernel 1: QKV GEMM  (8192 x 3072 x 1024), epilogue scatters to q/k/v
// 128x128 block tile, 16 k-slice, 256 threads, 8x8 per-thread microtile
// =====================================================================
__global__ __launch_bounds__(256)
void qkv_gemm(const float* __restrict__ x, const float* __restrict__ w,
              const float* __restrict__ bias) {
    __shared__ float As[16][128];
    __shared__ float Bs[16][128];

    const int tid = threadIdx.x;
    const int tx = tid & 15;          // 0..15  -> 8 cols each
    const int ty = tid >> 4;          // 0..15  -> 8 rows each
    const int bm0 = blockIdx.y * 128;
    const int bn0 = blockIdx.x * 128;

    float acc[8][8];
#pragma unroll
    for (int i = 0; i < 8; ++i)
#pragma unroll
        for (int j = 0; j < 8; ++j) acc[i][j] = 0.f;

    for (int kt = 0; kt < CDIM; kt += 16) {
        // load A tile (128 rows x 16 k), transpose into As[k][m]
#pragma unroll
        for (int it = 0; it < 2; ++it) {
            int idx = tid + it * 256;           // 0..511
            int r  = idx >> 2;                  // row in tile
            int kq = (idx & 3) << 2;            // k offset (0,4,8,12)
            float4 v = *(const float4*)(x + (size_t)(bm0 + r) * CDIM + kt + kq);
            As[kq + 0][r] = v.x; As[kq + 1][r] = v.y;
            As[kq + 2][r] = v.z; As[kq + 3][r] = v.w;
        }
        // load B tile (16 k x 128 cols), direct
#pragma unroll
        for (int it = 0; it < 2; ++it) {
            int idx = tid + it * 256;
            int kr = idx >> 5;                  // 0..15
            int c  = (idx & 31) << 2;           // 0..124
            *(float4*)&Bs[kr][c] =
                *(const float4*)(w + (size_t)(kt + kr) * QKVN + bn0 + c);
        }
        __syncthreads();

#pragma unroll
        for (int kk = 0; kk < 16; ++kk) {
            float a[8], b[8];
            *(float4*)(a)     = *(float4*)&As[kk][ty * 8];
            *(float4*)(a + 4) = *(float4*)&As[kk][ty * 8 + 4];
            *(float4*)(b)     = *(float4*)&Bs[kk][tx * 8];
            *(float4*)(b + 4) = *(float4*)&Bs[kk][tx * 8 + 4];
#pragma unroll
            for (int i = 0; i < 8; ++i)
#pragma unroll
                for (int j = 0; j < 8; ++j) acc[i][j] += a[i] * b[j];
        }
        __syncthreads();
    }

    // epilogue: add bias, scatter into q (pre-scaled), k, v  [B,H,N,D]
#pragma unroll
    for (int i = 0; i < 8; ++i) {
        int row = bm0 + ty * 8 + i;
        int bb = row >> 11;
        int n  = row & 2047;
#pragma unroll
        for (int jj = 0; jj < 8; jj += 4) {
            int col = bn0 + tx * 8 + jj;
            int t   = col >> 10;
            int rem = col & 1023;
            int h   = rem >> 6;
            int d   = rem & 63;
            float4 o;
            o.x = acc[i][jj + 0] + __ldg(bias + col + 0);
            o.y = acc[i][jj + 1] + __ldg(bias + col + 1);
            o.z = acc[i][jj + 2] + __ldg(bias + col + 2);
            o.w = acc[i][jj + 3] + __ldg(bias + col + 3);
            size_t dst = ((size_t)((bb * NH + h) * SEQ + n)) * HD + d;
            if (t == 0) {
                o.x *= SM_SCALE; o.y *= SM_SCALE; o.z *= SM_SCALE; o.w *= SM_SCALE;
                *(float4*)&g_q[dst] = o;
            } else if (t == 1) {
                *(float4*)&g_k[dst] = o;
            } else {
                *(float4*)&g_v[dst] = o;
            }
        }
    }
}

// =====================================================================
// Kernel 2: flash attention, one query row per thread.
// block = 128 threads = 128 q rows; grid = (SEQ/128, B*H)
// K/V tiles of 64 keys staged in smem; online softmax in chunks of 16.
// q is pre-scaled by SCALE*log2(e) -> softmax uses ex2 directly.
// =====================================================================
__global__ __launch_bounds__(128)
void attn_kernel() {
    __shared__ float Ks[64][64];
    __shared__ float Vs[64][64];

    const int tid = threadIdx.x;
    const int bh  = blockIdx.y;
    const int row = blockIdx.x * 128 + tid;

    const float* qp = g_q + ((size_t)bh * SEQ + row) * HD;
    float q[64], o[64];
#pragma unroll
    for (int d4 = 0; d4 < 64; d4 += 4) {
        float4 v = *(const float4*)(qp + d4);
        q[d4] = v.x; q[d4 + 1] = v.y; q[d4 + 2] = v.z; q[d4 + 3] = v.w;
    }
#pragma unroll
    for (int d = 0; d < 64; ++d) o[d] = 0.f;

    float m = -1e30f, l = 0.f;
    const float4* kbase = (const float4*)(g_k + (size_t)bh * SEQ * HD);
    const float4* vbase = (const float4*)(g_v + (size_t)bh * SEQ * HD);
    float4* Ks4 = (float4*)Ks;
    float4* Vs4 = (float4*)Vs;

#pragma unroll 1
    for (int kt = 0; kt < SEQ / 64; ++kt) {
        const float4* ks = kbase + (size_t)kt * 64 * 16;   // 64 rows * 16 float4
        const float4* vs = vbase + (size_t)kt * 64 * 16;
#pragma unroll
        for (int it = 0; it < 8; ++it) {
            Ks4[tid + it * 128] = ks[tid + it * 128];
            Vs4[tid + it * 128] = vs[tid + it * 128];
        }
        __syncthreads();

#pragma unroll 1
        for (int ch = 0; ch < 64; ch += 16) {
            float s[16];
#pragma unroll
            for (int j = 0; j < 16; ++j) {
                const float* kr = &Ks[ch + j][0];
                float a0 = 0.f, a1 = 0.f;
#pragma unroll
                for (int d4 = 0; d4 < 64; d4 += 8) {
                    float4 k0 = *(const float4*)(kr + d4);
                    float4 k1 = *(const float4*)(kr + d4 + 4);
                    a0 += q[d4 + 0] * k0.x; a0 += q[d4 + 1] * k0.y;
                    a0 += q[d4 + 2] * k0.z; a0 += q[d4 + 3] * k0.w;
                    a1 += q[d4 + 4] * k1.x; a1 += q[d4 + 5] * k1.y;
                    a1 += q[d4 + 6] * k1.z; a1 += q[d4 + 7] * k1.w;
                }
                s[j] = a0 + a1;
            }
            float cmax = s[0];
#pragma unroll
            for (int j = 1; j < 16; ++j) cmax = fmaxf(cmax, s[j]);
            float mnew = fmaxf(m, cmax);
            float scale = ex2f(m - mnew);
            float psum = 0.f;
#pragma unroll
            for (int j = 0; j < 16; ++j) {
                s[j] = ex2f(s[j] - mnew);
                psum += s[j];
            }
            l = l * scale + psum;
#pragma unroll
            for (int d = 0; d < 64; ++d) o[d] *= scale;
#pragma unroll
            for (int j = 0; j < 16; ++j) {
                const float* vr = &Vs[ch + j][0];
                float p = s[j];
#pragma unroll
                for (int d4 = 0; d4 < 64; d4 += 4) {
                    float4 v4 = *(const float4*)(vr + d4);
                    o[d4 + 0] += p * v4.x; o[d4 + 1] += p * v4.y;
                    o[d4 + 2] += p * v4.z; o[d4 + 3] += p * v4.w;
                }
            }
            m = mnew;
        }
        __syncthreads();
    }

    float inv = 1.f / l;
    int b = bh >> 4, h = bh & 15;
    float* op = g_att + ((size_t)(b * SEQ + row)) * CDIM + h * HD;
#pragma unroll
    for (int d4 = 0; d4 < 64; d4 += 4) {
        float4 ov;
        ov.x = o[d4 + 0] * inv; ov.y = o[d4 + 1] * inv;
        ov.z = o[d4 + 2] * inv; ov.w = o[d4 + 3] * inv;
        *(float4*)(op + d4) = ov;
    }
}

// =====================================================================
// Kernel 3: output projection GEMM (8192 x 1024 x 1024) + bias -> d_out
// =====================================================================
__global__ __launch_bounds__(256)
void proj_gemm(const float* __restrict__ w, const float* __restrict__ bias,
               float* __restrict__ out) {
    __shared__ float As[16][128];
    __shared__ float Bs[16][128];

    const int tid = threadIdx.x;
    const int tx = tid & 15;
    const int ty = tid >> 4;
    const int bm0 = blockIdx.y * 128;
    const int bn0 = blockIdx.x * 128;

    float acc[8][8];
#pragma unroll
    for (int i = 0; i < 8; ++i)
#pragma unroll
        for (int j = 0; j < 8; ++j) acc[i][j] = 0.f;

    for (int kt = 0; kt < CDIM; kt += 16) {
#pragma unroll
        for (int it = 0; it < 2; ++it) {
            int idx = tid + it * 256;
            int r  = idx >> 2;
            int kq = (idx & 3) << 2;
            float4 v = *(const float4*)(g_att + (size_t)(bm0 + r) * CDIM + kt + kq);
            As[kq + 0][r] = v.x; As[kq + 1][r] = v.y;
            As[kq + 2][r] = v.z; As[kq + 3][r] = v.w;
        }
#pragma unroll
        for (int it = 0; it < 2; ++it) {
            int idx = tid + it * 256;
            int kr = idx >> 5;
            int c  = (idx & 31) << 2;
            *(float4*)&Bs[kr][c] =
                *(const float4*)(w + (size_t)(kt + kr) * CDIM + bn0 + c);
        }
        __syncthreads();

#pragma unroll
        for (int kk = 0; kk < 16; ++kk) {
            float a[8], b[8];
            *(float4*)(a)     = *(float4*)&As[kk][ty * 8];
            *(float4*)(a + 4) = *(float4*)&As[kk][ty * 8 + 4];
            *(float4*)(b)     = *(float4*)&Bs[kk][tx * 8];
            *(float4*)(b + 4) = *(float4*)&Bs[kk][tx * 8 + 4];
#pragma unroll
            for (int i = 0; i < 8; ++i)
#pragma unroll
                for (int j = 0; j < 8; ++j) acc[i][j] += a[i] * b[j];
        }
        __syncthreads();
    }

#pragma unroll
    for (int i = 0; i < 8; ++i) {
        int row = bm0 + ty * 8 + i;
#pragma unroll
        for (int jj = 0; jj < 8; jj += 4) {
            int col = bn0 + tx * 8 + jj;
            float4 o;
            o.x = acc[i][jj + 0] + __ldg(bias + col + 0);
            o.y = acc[i][jj + 1] + __ldg(bias + col + 1);
            o.z = acc[i][jj + 2] + __ldg(bias + col + 2);
            o.w = acc[i][jj + 3] + __ldg(bias + col + 3);
            *(float4*)(out + (size_t)row * CDIM + col) = o;
        }
    }
}

// =====================================================================
extern "C" void kernel_launch(void* const* d_in, const int* in_sizes, int n_in,
                              void* d_out, int out_size) {
    const float* x      = (const float*)d_in[0];
    const float* w_qkv  = (const float*)d_in[1];
    const float* b_qkv  = (const float*)d_in[2];
    const float* w_proj = (const float*)d_in[3];
    const float* b_proj = (const float*)d_in[4];
    float* out = (float*)d_out;

    qkv_gemm<<<dim3(QKVN / 128, MROWS / 128), 256>>>(x, w_qkv, b_qkv);
    attn_kernel<<<dim3(SEQ / 128, BATCH * NH), 128>>>();
    proj_gemm<<<dim3(CDIM / 128, MROWS / 128), 256>>>(w_proj, b_proj, out);
}